// round 17
// baseline (speedup 1.0000x reference)
#include <cuda_runtime.h>
#include <stdint.h>

#define BATCH 2048
#define HW81  81
#define CDIM  512
#define HID   256
#define NSM   152                 /* GB300 SM count (R15: 152 CTAs co-resident) */

// W pre-rounded to tf32 (fp32 bit patterns), [256][512]
__device__ float g_Wt[HID * CDIM];

// ---------------------------------------------------------------------------
// helpers
// ---------------------------------------------------------------------------
__device__ __forceinline__ uint32_t f2tf32(float f) {
    uint32_t u;
    asm("cvt.rna.tf32.f32 %0, %1;" : "=r"(u) : "f"(f));
    return u;
}

__device__ __forceinline__ uint32_t smem_u32(const void* p) {
    uint32_t a;
    asm("{ .reg .u64 t; cvta.to.shared.u64 t, %1; cvt.u32.u64 %0, t; }" : "=r"(a) : "l"(p));
    return a;
}

__device__ __forceinline__ void cp16(uint32_t dst, const void* src) {
    asm volatile("cp.async.cg.shared.global [%0], [%1], 16;" :: "r"(dst), "l"(src));
}

__device__ __forceinline__ void mma_tf32(float* c, uint32_t a0, uint32_t a1,
                                         uint32_t a2, uint32_t a3,
                                         uint32_t b0, uint32_t b1) {
    asm volatile(
        "mma.sync.aligned.m16n8k8.row.col.f32.tf32.tf32.f32 "
        "{%0,%1,%2,%3}, {%4,%5,%6,%7}, {%8,%9}, {%0,%1,%2,%3};\n"
        : "+f"(c[0]), "+f"(c[1]), "+f"(c[2]), "+f"(c[3])
        : "r"(a0), "r"(a1), "r"(a2), "r"(a3), "r"(b0), "r"(b1));
}

// ---------------------------------------------------------------------------
// Kernel 0: round W to tf32 (RNA) once.
// ---------------------------------------------------------------------------
__global__ void wprep_kernel(const float* __restrict__ Wf) {
    int i = blockIdx.x * 512 + threadIdx.x;
    g_Wt[i] = __uint_as_float(f2tf32(Wf[i]));
}

// ---------------------------------------------------------------------------
// Persistent fused kernel: grid = NSM, 1 CTA/SM, 256 threads.
// Each CTA owns a contiguous batch span. For batch b, the 16-iteration tf32
// mainloop (rows 0..79 MMA + row 80 FMA) also executes one ATTN SLICE of
// batch b-1 per iteration, hidden in the tensor-pipe drain:
//   it 0-8: syrk patch p  |  it 9: shfl reduce  |  it 10: attn build
//   it 11: attn^2         |  it 12: double softmax -> P
//   it 13-15: epilogue (3 patches each): out = P @ x
// Mainloop barriers provide all inter-slice ordering. sY is its own region
// (no reuse), so writeback(b) never races slices (last Y reader = it 8).
// smem: staging 97056B + Y 82944B = 180000B dyn.
// ---------------------------------------------------------------------------
#define KSTG     32
#define STRIDE   36
#define A_ROWS   81
#define OFF_A0   0
#define OFF_B0   (A_ROWS * STRIDE)               /* 2916  */
#define OFF_A1   (OFF_B0 + HID * STRIDE)         /* 12132 */
#define OFF_B1   (OFF_A1 + A_ROWS * STRIDE)      /* 15048 */
#define STAGE_FLOATS (OFF_B1 + HID * STRIDE)     /* 24264 floats */
#define SMEM_FLOATS  (STAGE_FLOATS + HW81 * HID) /* 45000 floats = 180000 B */

__global__ __launch_bounds__(256, 1)
void fused_persist(const float* __restrict__ X, const float* __restrict__ bfc,
                   float* __restrict__ out)
{
    extern __shared__ __align__(16) float smem[];
    float* sY = smem + STAGE_FLOATS;             // [81][256]
    __shared__ float sBias[HID];
    __shared__ float sRed[8][45];
    __shared__ float sAttn[81];
    __shared__ float sB2[81];
    __shared__ __align__(16) float sPp[9 * 12];
    __shared__ int sRM[81];                      // sRM[p*9+q] = rowmap(q,p)

    const int tid  = threadIdx.x;
    const int lane = tid & 31;
    const int warp = tid >> 5;
    const uint32_t sbase = smem_u32(smem);

    const int b0   = (BATCH * blockIdx.x) / NSM;
    const int bEnd = (BATCH * (blockIdx.x + 1)) / NSM;

    sBias[tid] = __ldg(bfc + tid);
    if (tid < 81) {
        int p = tid / 9, q = tid % 9;
        sRM[tid] = (3 * (q / 3) + p / 3) * 9 + 3 * (q % 3) + (p % 3);
    }

    float sa[45];                                // syrk partials (persist its 0..9)

    // one attn slice of the PREVIOUS batch; contains no barriers.
    auto attn_slice = [&](int sl, const float* Xp, float* Op) {
        if (sl <= 8) {
            const int p = sl;
            if (sl == 0) {
#pragma unroll
                for (int i = 0; i < 45; i++) sa[i] = 0.f;
            }
            float z[9];
#pragma unroll
            for (int q = 0; q < 9; q++) z[q] = sY[sRM[p * 9 + q] * HID + tid];
            int ci = 0;
#pragma unroll
            for (int n = 0; n < 9; n++)
#pragma unroll
                for (int m = n; m < 9; m++) sa[ci++] += z[n] * z[m];
        } else if (sl == 9) {
#pragma unroll
            for (int i = 0; i < 45; i++) {
                float v = sa[i];
#pragma unroll
                for (int o = 16; o > 0; o >>= 1) v += __shfl_xor_sync(0xffffffffu, v, o);
                if (lane == 0) sRed[warp][i] = v;
            }
        } else if (sl == 10) {
            if (tid < 45) {
                float s = 0.f;
#pragma unroll
                for (int w = 0; w < 8; w++) s += sRed[w][tid];
                int n = 0, m = tid;
                while (m >= 9 - n) { m -= (9 - n); n++; }
                m += n;
                float val = s * (1.0f / 48.0f);  // 1/sqrt(hidden*P)
                if (n == m) val -= 100.0f;       // diagonal suppression
                sAttn[n * 9 + m] = val;
                sAttn[m * 9 + n] = val;
            }
        } else if (sl == 11) {
            if (tid < 81) {
                int n = tid / 9, k = tid % 9;
                float s = 0.f;
#pragma unroll
                for (int m = 0; m < 9; m++) s += sAttn[n * 9 + m] * sAttn[k * 9 + m];
                sB2[tid] = s * (1.0f / 3.0f);
            }
        } else if (sl == 12) {
            if (tid < 9) {
                int n = tid;
                float mx = -1e30f;
#pragma unroll
                for (int k = 0; k < 9; k++) mx = fmaxf(mx, sB2[n * 9 + k]);
                float e[9]; float se = 0.f;
#pragma unroll
                for (int k = 0; k < 9; k++) { e[k] = expf(sB2[n * 9 + k] - mx); se += e[k]; }
                float inv = 1.0f / se;
                float L[9]; float mx2 = -1e30f;
#pragma unroll
                for (int k = 0; k < 9; k++) {
                    L[k] = sAttn[n * 9 + k] + e[k] * inv;
                    mx2 = fmaxf(mx2, L[k]);
                }
                float e2[9]; float s2 = 0.f;
#pragma unroll
                for (int k = 0; k < 9; k++) { e2[k] = expf(L[k] - mx2); s2 += e2[k]; }
                float inv2 = 1.0f / s2;
#pragma unroll
                for (int k = 0; k < 9; k++) sPp[n * 12 + k] = e2[k] * inv2;
            }
        } else {                                 // sl 13..15: epilogue
            const float2* Xp2 = (const float2*)Xp;
            float2* Op2 = (float2*)Op;
#pragma unroll
            for (int j = 0; j < 3; j++) {
                const int p = 3 * (sl - 13) + j;
                float2 v[9];
#pragma unroll
                for (int m = 0; m < 9; m++)
                    v[m] = Xp2[sRM[p * 9 + m] * 256 + tid];
#pragma unroll
                for (int n = 0; n < 9; n++) {
                    float4 w0 = *(const float4*)&sPp[n * 12 + 0];
                    float4 w1 = *(const float4*)&sPp[n * 12 + 4];
                    float  w2 = sPp[n * 12 + 8];
                    float2 o;
                    o.x = w0.x * v[0].x + w0.y * v[1].x + w0.z * v[2].x + w0.w * v[3].x
                        + w1.x * v[4].x + w1.y * v[5].x + w1.z * v[6].x + w1.w * v[7].x
                        + w2 * v[8].x;
                    o.y = w0.x * v[0].y + w0.y * v[1].y + w0.z * v[2].y + w0.w * v[3].y
                        + w1.x * v[4].y + w1.y * v[5].y + w1.z * v[6].y + w1.w * v[7].y
                        + w2 * v[8].y;
                    Op2[sRM[p * 9 + n] * 256 + tid] = o;
                }
            }
        }
    };

#define ISSUE_STAGE(XB, IT, OFFA, OFFB)                                      \
    do {                                                                     \
        const int k0 = (IT) * KSTG;                                          \
        _Pragma("unroll")                                                    \
        for (int i = 0; i < 3; i++) {                                        \
            int f = i * 256 + tid;                                           \
            if (f < 648) {                                                   \
                int r = f >> 3, j = (f & 7) << 2;                            \
                cp16(sbase + ((OFFA) + r * STRIDE + j) * 4,                  \
                     (XB) + (size_t)r * CDIM + k0 + j);                      \
            }                                                                \
        }                                                                    \
        _Pragma("unroll")                                                    \
        for (int i = 0; i < 8; i++) {                                        \
            int f = i * 256 + tid;                                           \
            int n = f >> 3, j = (f & 7) << 2;                                \
            cp16(sbase + ((OFFB) + n * STRIDE + j) * 4,                      \
                 g_Wt + (size_t)n * CDIM + k0 + j);                          \
        }                                                                    \
        asm volatile("cp.async.commit_group;" ::: "memory");                 \
    } while (0)

    const int ar = lane >> 2;            // 0..7
    const int ac = lane & 3;
    const int bn = warp * 32 + (lane >> 2);

    // prologue: first two stages of batch b0
    {
        const float* Xb0 = X + (size_t)b0 * (HW81 * CDIM);
        ISSUE_STAGE(Xb0, 0, OFF_A0, OFF_B0);
        ISSUE_STAGE(Xb0, 1, OFF_A1, OFF_B1);
    }

    for (int bi = b0; bi < bEnd; bi++) {
        const float* Xb    = X + (size_t)bi * (HW81 * CDIM);
        const float* Xnext = X + (size_t)(bi + 1) * (HW81 * CDIM);
        const float* Xprev = X + (size_t)(bi - 1) * (HW81 * CDIM);
        float*       Oprev = out + (size_t)(bi - 1) * (HW81 * CDIM);
        const bool hasPrev = (bi > b0);
        const bool hasNext = (bi + 1 < bEnd);

        float acc[5][4][4];
#pragma unroll
        for (int a = 0; a < 5; a++)
#pragma unroll
            for (int c = 0; c < 4; c++)
#pragma unroll
                for (int d = 0; d < 4; d++) acc[a][c][d] = 0.f;
        float s80 = 0.f;

        for (int it = 0; it < 16; it++) {
            if (hasNext || it < 15) asm volatile("cp.async.wait_group 1;" ::: "memory");
            else                    asm volatile("cp.async.wait_group 0;" ::: "memory");
            __syncthreads();

            const float*    sA  = smem + ((it & 1) ? OFF_A1 : OFF_A0);
            const uint32_t* sB  = (const uint32_t*)(smem + ((it & 1) ? OFF_B1 : OFF_B0));
            const float*    sBf = (const float*)sB;

#pragma unroll
            for (int kk = 0; kk < 4; kk++) {
                const int c = kk * 8 + ac;
                uint32_t bf[4][2];
#pragma unroll
                for (int nt = 0; nt < 4; nt++) {
                    bf[nt][0] = sB[(bn + nt * 8) * STRIDE + c];
                    bf[nt][1] = sB[(bn + nt * 8) * STRIDE + c + 4];
                }
#pragma unroll
                for (int mt = 0; mt < 5; mt++) {
                    const int r = ar + mt * 16;
                    uint32_t a0 = f2tf32(sA[r * STRIDE + c]);
                    uint32_t a1 = f2tf32(sA[(r + 8) * STRIDE + c]);
                    uint32_t a2 = f2tf32(sA[r * STRIDE + c + 4]);
                    uint32_t a3 = f2tf32(sA[(r + 8) * STRIDE + c + 4]);
#pragma unroll
                    for (int nt = 0; nt < 4; nt++)
                        mma_tf32(acc[mt][nt], a0, a1, a2, a3, bf[nt][0], bf[nt][1]);
                }
            }

            // row 80 via FMA: thread owns column `tid`
#pragma unroll
            for (int k4 = 0; k4 < 8; k4++) {
                float4 av = *(const float4*)&sA[80 * STRIDE + k4 * 4];
                float4 wv = *(const float4*)&sBf[tid * STRIDE + k4 * 4];
                s80 += av.x * wv.x + av.y * wv.y + av.z * wv.z + av.w * wv.w;
            }

            // attn slice for batch bi-1, hidden under the tensor drain
            if (hasPrev) attn_slice(it, Xprev, Oprev);

            __syncthreads();

            if (it < 14) {
                if (it & 1) ISSUE_STAGE(Xb, it + 2, OFF_A1, OFF_B1);
                else        ISSUE_STAGE(Xb, it + 2, OFF_A0, OFF_B0);
            } else if (hasNext) {
                if (it & 1) ISSUE_STAGE(Xnext, it - 14, OFF_A1, OFF_B1);
                else        ISSUE_STAGE(Xnext, it - 14, OFF_A0, OFF_B0);
            }
        }

        // writeback Y(bi) + bias (sY region: last reader was slice 8, barriers since)
#pragma unroll
        for (int nt = 0; nt < 4; nt++) {
            const int cc = warp * 32 + nt * 8 + ((lane & 3) << 1);
            const float bb0 = sBias[cc];
            const float bb1 = sBias[cc + 1];
#pragma unroll
            for (int mt = 0; mt < 5; mt++) {
                const int r = ar + mt * 16;
                sY[r * HID + cc]           = acc[mt][nt][0] + bb0;
                sY[r * HID + cc + 1]       = acc[mt][nt][1] + bb1;
                sY[(r + 8) * HID + cc]     = acc[mt][nt][2] + bb0;
                sY[(r + 8) * HID + cc + 1] = acc[mt][nt][3] + bb1;
            }
        }
        sY[80 * HID + tid] = s80 + sBias[tid];
        // visibility to next batch's slice 0 is provided by its it=0 barrier
    }

    // tail: full attn for the final batch
    __syncthreads();
    {
        const float* Xprev = X + (size_t)(bEnd - 1) * (HW81 * CDIM);
        float*       Oprev = out + (size_t)(bEnd - 1) * (HW81 * CDIM);
        for (int sl = 0; sl < 16; sl++) {
            attn_slice(sl, Xprev, Oprev);
            __syncthreads();
        }
    }
}

// ---------------------------------------------------------------------------
extern "C" void kernel_launch(void* const* d_in, const int* in_sizes, int n_in,
                              void* d_out, int out_size)
{
    const float* x   = (const float*)d_in[0];   // [2048, 9, 9, 512] fp32
    const float* Wf  = (const float*)d_in[1];   // [256, 512] fp32
    const float* bfc = (const float*)d_in[2];   // [256] fp32
    float* out = (float*)d_out;

    static bool init = false;
    if (!init) {
        cudaFuncSetAttribute(fused_persist,
                             cudaFuncAttributeMaxDynamicSharedMemorySize,
                             SMEM_FLOATS * 4);
        init = true;
    }

    wprep_kernel<<<256, 512>>>(Wf);
    fused_persist<<<NSM, 256, SMEM_FLOATS * 4>>>(x, bfc, out);
}